// round 1
// baseline (speedup 1.0000x reference)
#include <cuda_runtime.h>
#include <math.h>

#define BATCH 8192
#define NMAX  16
#define TSTEPS 4
#define DIN   4
#define DEMB  64
#define HID   128
#define G4    512           // 4*HID gate width
#define NSEQ  (BATCH*(1+NMAX))   // 139264 sequences (targets + neighbors)

// ---------------- scratch (device globals: allocation-free) ----------------
__device__ float g_E[(size_t)NSEQ*TSTEPS*DEMB]; // embedded inputs  [seq][t][64]
__device__ float g_H[(size_t)NSEQ*HID];         // hidden state     [seq][128]
__device__ float g_C[(size_t)NSEQ*HID];         // cell state       [seq][128]
__device__ float g_WT[(DEMB+HID)*G4];           // transposed weights [k][512]; k<64 -> W_ih, else W_hh
__device__ float g_bsum[G4];                    // b_ih + b_hh

// ---------------- prep: transpose weights, combine biases ----------------
__global__ void prep_kernel(const float* __restrict__ Wih, const float* __restrict__ Whh,
                            const float* __restrict__ bih, const float* __restrict__ bhh) {
    int i = blockIdx.x * blockDim.x + threadIdx.x;
    if (i < (DEMB + HID) * G4) {
        int k = i / G4, c = i % G4;
        g_WT[i] = (k < DEMB) ? Wih[c*DEMB + k] : Whh[c*HID + (k - DEMB)];
    }
    if (i < G4) g_bsum[i] = bih[i] + bhh[i];
}

// ---------------- embed: relu(x @ We^T + be) for target + neighbors ----------------
__global__ void embed_kernel(const float* __restrict__ x, const float* __restrict__ nb,
                             const float* __restrict__ We, const float* __restrict__ be) {
    int idx = blockIdx.x * blockDim.x + threadIdx.x;
    if (idx >= NSEQ * TSTEPS * DEMB) return;
    int j   = idx & 63;         // embed dim
    int st  = idx >> 6;         // seq*T + t
    int t   = st & 3;
    int seq = st >> 2;
    const float* src = (seq < BATCH) ? (x  + ((size_t)seq * TSTEPS + t) * DIN)
                                     : (nb + ((size_t)(seq - BATCH) * TSTEPS + t) * DIN);
    float v = be[j];
#pragma unroll
    for (int d = 0; d < 4; d++) v = fmaf(src[d], We[j*4 + d], v);
    g_E[idx] = fmaxf(v, 0.f);
}

// ---------------- fused LSTM step: g = E_t@Wih^T + H@Whh^T + b; gates; update H,C ----------------
// Block: 256 threads, 16 rows (sequences). Each thread: 4 rows x (2 cols x 4 gates) = 32 accumulators.
__device__ __forceinline__ float sigf(float v) { return 1.f / (1.f + expf(-v)); }

__global__ __launch_bounds__(256) void lstm_step_kernel(int t) {
    __shared__ float As[16][DEMB];   // E rows for this timestep
    __shared__ float Hs[16][HID];    // previous hidden
    __shared__ float Ws[16][G4];     // streamed weight chunk (16 k-rows x 512 cols)

    const int tid = threadIdx.x;
    const int tx  = tid & 63;        // column group: j = 2*tx (+jj), per gate
    const int ty  = tid >> 6;        // row group: rows ty, ty+4, ty+8, ty+12
    const int row0 = blockIdx.x * 16;

    // load A (E slice): 16 rows x 64 floats, float4-coalesced
    {
        int rr = tid >> 4, c4 = (tid & 15) * 4;
        *(float4*)&As[rr][c4] = *(const float4*)&g_E[((row0 + rr) * TSTEPS + t) * DEMB + c4];
    }
    if (t > 0) {
#pragma unroll
        for (int i = 0; i < 2; i++) {
            int idx = tid + 256 * i;
            int rr = idx >> 5, c4 = (idx & 31) * 4;
            *(float4*)&Hs[rr][c4] = *(const float4*)&g_H[(row0 + rr) * HID + c4];
        }
    }

    float acc[4][4][2];   // [rowq][gate][jj]
#pragma unroll
    for (int g = 0; g < 4; g++) {
        float b0 = g_bsum[g*128 + 2*tx], b1v = g_bsum[g*128 + 2*tx + 1];
#pragma unroll
        for (int q = 0; q < 4; q++) { acc[q][g][0] = b0; acc[q][g][1] = b1v; }
    }

#define GEMM_CHUNK(AARR, aoff, wrow)                                                    \
    do {                                                                                \
        __syncthreads();                                                                \
        _Pragma("unroll")                                                               \
        for (int i = 0; i < 8; i++)                                                     \
            ((float4*)&Ws[0][0])[tid + 256*i] =                                         \
                ((const float4*)&g_WT[(wrow) * G4])[tid + 256*i];                       \
        __syncthreads();                                                                \
        _Pragma("unroll")                                                               \
        for (int kk = 0; kk < 16; kk++) {                                               \
            float a0 = AARR[ty     ][(aoff) + kk];                                      \
            float a1 = AARR[ty + 4 ][(aoff) + kk];                                      \
            float a2 = AARR[ty + 8 ][(aoff) + kk];                                      \
            float a3 = AARR[ty + 12][(aoff) + kk];                                      \
            _Pragma("unroll")                                                           \
            for (int g = 0; g < 4; g++) {                                               \
                float2 w = *(const float2*)&Ws[kk][g*128 + 2*tx];                       \
                acc[0][g][0] = fmaf(a0, w.x, acc[0][g][0]);                             \
                acc[0][g][1] = fmaf(a0, w.y, acc[0][g][1]);                             \
                acc[1][g][0] = fmaf(a1, w.x, acc[1][g][0]);                             \
                acc[1][g][1] = fmaf(a1, w.y, acc[1][g][1]);                             \
                acc[2][g][0] = fmaf(a2, w.x, acc[2][g][0]);                             \
                acc[2][g][1] = fmaf(a2, w.y, acc[2][g][1]);                             \
                acc[3][g][0] = fmaf(a3, w.x, acc[3][g][0]);                             \
                acc[3][g][1] = fmaf(a3, w.y, acc[3][g][1]);                             \
            }                                                                           \
        }                                                                               \
    } while (0)

    // phase 1: K = 0..63 (embedded input part)
    for (int kb = 0; kb < DEMB; kb += 16) GEMM_CHUNK(As, kb, kb);
    // phase 2: K = 64..191 (recurrent part); skipped at t==0 since h_prev == 0
    if (t > 0)
        for (int kb = 0; kb < HID; kb += 16) GEMM_CHUNK(Hs, kb, DEMB + kb);
#undef GEMM_CHUNK

    // gates + state update (PyTorch order i, f, g, o)
    const int j = 2 * tx;
#pragma unroll
    for (int q = 0; q < 4; q++) {
        int r = row0 + ty + 4*q;
#pragma unroll
        for (int jj = 0; jj < 2; jj++) {
            float iv = sigf(acc[q][0][jj]);
            float fv = sigf(acc[q][1][jj]);
            float gv = tanhf(acc[q][2][jj]);
            float ov = sigf(acc[q][3][jj]);
            float cp = (t == 0) ? 0.f : g_C[r * HID + j + jj];
            float c  = fmaf(fv, cp, iv * gv);
            g_C[r * HID + j + jj] = c;
            g_H[r * HID + j + jj] = ov * tanhf(c);
        }
    }
}

// ---------------- head: masked mean pool, 2-layer MLP, softmax probs ----------------
// 4 batch rows per block (amortizes W1 L2 traffic), 128 threads.
__global__ __launch_bounds__(128) void head_kernel(
        const int* __restrict__ mask,
        const float* __restrict__ W1, const float* __restrict__ b1,
        const float* __restrict__ W2, const float* __restrict__ b2,
        const float* __restrict__ Wp, const float* __restrict__ bp,
        float* __restrict__ out) {
    __shared__ float hf[4][2*HID];
    __shared__ float hid[4][HID];
    __shared__ float lg[4][3];

    const int j  = threadIdx.x;    // 0..127
    const int b0 = blockIdx.x * 4;

#pragma unroll
    for (int r = 0; r < 4; r++) {
        int b = b0 + r;
        hf[r][j] = g_H[b * HID + j];                        // target hidden
        float s = 0.f, cnt = 0.f;
#pragma unroll
        for (int n = 0; n < NMAX; n++) {
            float m = (float)mask[b * NMAX + n];
            s   = fmaf(m, g_H[(BATCH + b * NMAX + n) * HID + j], s);
            cnt += m;
        }
        hf[r][HID + j] = s / fmaxf(cnt, 1.f);               // masked mean pool
    }
    __syncthreads();

    // hidden = relu(hf @ W1^T + b1), W1 row reused across the 4 batch rows
    {
        float a0 = b1[j], a1 = a0, a2 = a0, a3 = a0;
        for (int k = 0; k < 2*HID; k++) {
            float w = W1[j * 2*HID + k];
            a0 = fmaf(w, hf[0][k], a0);
            a1 = fmaf(w, hf[1][k], a1);
            a2 = fmaf(w, hf[2][k], a2);
            a3 = fmaf(w, hf[3][k], a3);
        }
        hid[0][j] = fmaxf(a0, 0.f); hid[1][j] = fmaxf(a1, 0.f);
        hid[2][j] = fmaxf(a2, 0.f); hid[3][j] = fmaxf(a3, 0.f);
    }
    __syncthreads();

    // traj = hid @ W2^T + b2  -> out[0 .. B*36)
    for (int idx = j; idx < 4 * 36; idx += 128) {
        int r = idx / 36, o = idx % 36;
        float a = b2[o];
        for (int k = 0; k < HID; k++) a = fmaf(W2[o * HID + k], hid[r][k], a);
        out[(size_t)(b0 + r) * 36 + o] = a;
    }
    // logits -> softmax over K=3 -> out[B*36 .. B*36 + B*3)
    if (j < 12) {
        int r = j / 3, kk = j % 3;
        float a = bp[kk];
        for (int k = 0; k < 2*HID; k++) a = fmaf(Wp[kk * 2*HID + k], hf[r][k], a);
        lg[r][kk] = a;
    }
    __syncthreads();
    if (j < 12) {
        int r = j / 3, kk = j % 3;
        float m  = fmaxf(lg[r][0], fmaxf(lg[r][1], lg[r][2]));
        float e0 = expf(lg[r][0] - m), e1 = expf(lg[r][1] - m), e2 = expf(lg[r][2] - m);
        float e  = (kk == 0) ? e0 : ((kk == 1) ? e1 : e2);
        out[(size_t)BATCH * 36 + (size_t)(b0 + r) * 3 + kk] = e / (e0 + e1 + e2);
    }
}

// ---------------- launch ----------------
extern "C" void kernel_launch(void* const* d_in, const int* in_sizes, int n_in,
                              void* d_out, int out_size) {
    const float* x    = (const float*)d_in[0];
    const float* nb   = (const float*)d_in[1];
    const int*   mask = (const int*)  d_in[2];
    const float* We   = (const float*)d_in[3];
    const float* be   = (const float*)d_in[4];
    const float* Wih  = (const float*)d_in[5];
    const float* Whh  = (const float*)d_in[6];
    const float* bih  = (const float*)d_in[7];
    const float* bhh  = (const float*)d_in[8];
    const float* W1   = (const float*)d_in[9];
    const float* b1   = (const float*)d_in[10];
    const float* W2   = (const float*)d_in[11];
    const float* b2   = (const float*)d_in[12];
    const float* Wp   = (const float*)d_in[13];
    const float* bp   = (const float*)d_in[14];
    float* out = (float*)d_out;

    prep_kernel<<<((DEMB + HID) * G4 + 255) / 256, 256>>>(Wih, Whh, bih, bhh);

    long total = (long)NSEQ * TSTEPS * DEMB;
    embed_kernel<<<(unsigned)((total + 255) / 256), 256>>>(x, nb, We, be);

    for (int t = 0; t < TSTEPS; t++)
        lstm_step_kernel<<<NSEQ / 16, 256>>>(t);

    head_kernel<<<BATCH / 4, 128>>>(mask, W1, b1, W2, b2, Wp, bp, out);
}

// round 6
// speedup vs baseline: 1.1350x; 1.1350x over previous
#include <cuda_runtime.h>
#include <math.h>
#include <stdint.h>

#define BATCH 8192
#define NMAX  16
#define TSTEPS 4
#define DIN   4
#define DEMB  64
#define HID   128
#define G4    512
#define NSEQ  (BATCH*(1+NMAX))     // 139264 sequences
#define MTILE 64                   // sequences per CTA

// ---------------- scratch (device globals: allocation-free) ----------------
__device__ float g_E[(size_t)NSEQ*TSTEPS*DEMB]; // embedded inputs [seq][t][64], fp32
__device__ float g_H[(size_t)NSEQ*HID];         // FINAL hidden state only (row-major)
__device__ float g_W[(size_t)G4*192];           // combined weights [n][k0..191], fp32
__device__ float g_bsum[G4];                    // b_ih + b_hh

// ---------------- smem layout (floats) ----------------
// A: 12 chunks x [64 rows][20]   (k-chunk 16 + pad 4)        = 15360
// B: 2 bufs   x [512 n][20]                                  = 20480
// C: [64][132]                                               = 8448
// bias: 512
#define A_OFF 0
#define B_OFF 15360
#define C_OFF 35840
#define BS_OFF 44288
#define SMEM_FLOATS 44800
#define SMEM_BYTES (SMEM_FLOATS*4)   // 179200

__device__ __forceinline__ float tf32r(float x) {
    uint32_t r; asm("cvt.rna.tf32.f32 %0, %1;" : "=r"(r) : "f"(x));
    return __uint_as_float(r);
}
__device__ __forceinline__ void cp16(void* sdst, const void* gsrc) {
    uint32_t sa = (uint32_t)__cvta_generic_to_shared(sdst);
    asm volatile("cp.async.cg.shared.global [%0], [%1], 16;" :: "r"(sa), "l"(gsrc));
}
#define CP_COMMIT() asm volatile("cp.async.commit_group;" ::: "memory")
#define CP_WAIT(N)  asm volatile("cp.async.wait_group %0;" :: "n"(N) : "memory")

#define MMA_TF32(D, A0,A1,A2,A3, B0,B1)                                        \
    asm volatile(                                                              \
        "mma.sync.aligned.m16n8k8.row.col.f32.tf32.tf32.f32 "                  \
        "{%0,%1,%2,%3},{%4,%5,%6,%7},{%8,%9},{%0,%1,%2,%3};"                   \
        : "+f"((D)[0]), "+f"((D)[1]), "+f"((D)[2]), "+f"((D)[3])               \
        : "r"(A0), "r"(A1), "r"(A2), "r"(A3), "r"(B0), "r"(B1))

// ---------------- prep: combine weights (fp32), combine biases ----------------
__global__ void prep_kernel(const float* __restrict__ Wih, const float* __restrict__ Whh,
                            const float* __restrict__ bih, const float* __restrict__ bhh) {
    int i = blockIdx.x * 256 + threadIdx.x;
    if (i < G4 * 192) {
        int n = i / 192, k = i % 192;
        g_W[i] = (k < DEMB) ? Wih[n * DEMB + k] : Whh[n * HID + (k - DEMB)];
    }
    if (i < G4) g_bsum[i] = bih[i] + bhh[i];
}

// ---------------- embed: relu(x @ We^T + be), fp32 ----------------
__global__ void embed_kernel(const float* __restrict__ x, const float* __restrict__ nb,
                             const float* __restrict__ We, const float* __restrict__ be) {
    int idx = blockIdx.x * blockDim.x + threadIdx.x;
    if (idx >= NSEQ * TSTEPS * DEMB) return;
    int j   = idx & 63;
    int st  = idx >> 6;
    int t   = st & 3;
    int seq = st >> 2;
    const float* src = (seq < BATCH) ? (x  + ((size_t)seq * TSTEPS + t) * DIN)
                                     : (nb + ((size_t)(seq - BATCH) * TSTEPS + t) * DIN);
    float v = be[j];
#pragma unroll
    for (int d = 0; d < 4; d++) v = fmaf(src[d], We[j*4 + d], v);
    g_E[idx] = fmaxf(v, 0.f);
}

// ---------------- persistent 3xTF32 mma.sync LSTM ----------------
// CTA: 512 threads = 4 (m) x 4 (n) warps. Tile M=64 seqs x N=512 gates, K streamed 16-wide.
// Operands held fp32 in smem; hi/lo tf32 split derived in registers at fragment load.
// 3 MMAs per logical mma: ah*bh + al*bh + ah*bl  -> ~fp32 accuracy.
// Prefetch schedule (race-free): E(t+1) is issued only after ALL chunk reads of the
// current A-chunks are complete. At t=0 (nch=4) that forces it to c==nch-1, with a
// full CP_WAIT(0) at the last chunk since no younger group shields it.
__global__ void __launch_bounds__(512, 1)
lstm_fused_kernel() {
    extern __shared__ float sm[];
    float* As = sm + A_OFF;
    float* Bs = sm + B_OFF;
    float* Cs = sm + C_OFF;
    float* bs = sm + BS_OFF;

    const int tid  = threadIdx.x;
    const int lane = tid & 31, wid = tid >> 5;
    const int wm = wid & 3, wn = wid >> 2;
    const int g = lane >> 2, q = lane & 3;
    const int m0 = wm * 16;
    const int row0 = blockIdx.x * MTILE;

    bs[tid] = g_bsum[tid];

    // E chunk loader for step t -> A chunks 0..3 (k 0..63)
    auto load_E = [&](int t) {
#pragma unroll
        for (int i = 0; i < 2; i++) {
            int idx = tid + i * 512;
            int r = idx >> 4, k4 = idx & 15;          // k = k4*4
            cp16(&As[(k4 >> 2) * 1280 + r * 20 + (k4 & 3) * 4],
                 g_E + (((size_t)(row0 + r) * TSTEPS + t) * DEMB + k4 * 4));
        }
    };
    // B chunk loader: chunk c = k slice [16c, 16c+16) of combined weights, into buf
    auto load_B = [&](int c, int buf) {
        const float* w = g_W + (size_t)tid * 192 + c * 16;
        float* dst = Bs + buf * 10240 + tid * 20;
#pragma unroll
        for (int k4 = 0; k4 < 4; k4++) cp16(dst + k4 * 4, w + k4 * 4);
    };

    load_E(0); CP_COMMIT();
    load_B(0, 0); CP_COMMIT();
    load_B(1, 1); CP_COMMIT();

    for (int t = 0; t < TSTEPS; t++) {
        const int nch = (t == 0) ? 4 : 12;
        float acc[4][4][4];
#pragma unroll
        for (int a = 0; a < 4; a++)
#pragma unroll
            for (int b = 0; b < 4; b++)
#pragma unroll
                for (int c = 0; c < 4; c++) acc[a][b][c] = 0.f;

        for (int c = 0; c < nch; c++) {
            // last chunk at t=0 / t=3 has no younger in-flight group to shield it
            if ((t == 0 || t == 3) && c == nch - 1) { CP_WAIT(0); } else { CP_WAIT(1); }
            __syncthreads();

            // ---- 3xTF32 mma over chunk c ----
            const float* Ac = As + c * 1280;
            const float* Bc = Bs + (c & 1) * 10240;
#pragma unroll
            for (int ks = 0; ks < 2; ks++) {
                const float* ap = Ac + (m0 + g) * 20 + ks * 8 + q;
                float af0 = ap[0], af1 = ap[8 * 20], af2 = ap[4], af3 = ap[8 * 20 + 4];
                float h0 = tf32r(af0), h1 = tf32r(af1), h2 = tf32r(af2), h3 = tf32r(af3);
                uint32_t ah0 = __float_as_uint(h0), ah1 = __float_as_uint(h1);
                uint32_t ah2 = __float_as_uint(h2), ah3 = __float_as_uint(h3);
                uint32_t al0 = __float_as_uint(tf32r(af0 - h0));
                uint32_t al1 = __float_as_uint(tf32r(af1 - h1));
                uint32_t al2 = __float_as_uint(tf32r(af2 - h2));
                uint32_t al3 = __float_as_uint(tf32r(af3 - h3));
#pragma unroll
                for (int gate = 0; gate < 4; gate++)
#pragma unroll
                    for (int s = 0; s < 4; s++) {
                        const float* bp = Bc + (gate * 128 + wn * 32 + s * 8 + g) * 20 + ks * 8 + q;
                        float b0f = bp[0], b1f = bp[4];
                        float bh0f = tf32r(b0f), bh1f = tf32r(b1f);
                        uint32_t bh0 = __float_as_uint(bh0f), bh1 = __float_as_uint(bh1f);
                        uint32_t bl0 = __float_as_uint(tf32r(b0f - bh0f));
                        uint32_t bl1 = __float_as_uint(tf32r(b1f - bh1f));
                        float* d = acc[gate][s];
                        MMA_TF32(d, ah0, ah1, ah2, ah3, bh0, bh1);
                        MMA_TF32(d, al0, al1, al2, al3, bh0, bh1);
                        MMA_TF32(d, ah0, ah1, ah2, ah3, bl0, bl1);
                    }
            }
            __syncthreads();

            // ---- prefetch schedule (race-free) ----
            if (c + 2 < nch)                          { load_B(c + 2, c & 1); CP_COMMIT(); }
            else if (c == nch - 2 && t >= 1 && t < 3) { load_E(t + 1); CP_COMMIT(); }
            else if (c == nch - 1 && t < 3) {
                if (t == 0) { load_E(1); CP_COMMIT(); }   // A chunk reads all done (post-sync)
                load_B(0, 0); CP_COMMIT();
                load_B(1, 1); CP_COMMIT();
            }
        }

        // ---- register epilogue: gates -> c,h ----
#pragma unroll
        for (int s = 0; s < 4; s++)
#pragma unroll
            for (int h2 = 0; h2 < 2; h2++) {
                const int rl = m0 + g + h2 * 8;
#pragma unroll
                for (int e = 0; e < 2; e++) {
                    const int j  = wn * 32 + s * 8 + 2 * q + e;
                    const int ci = h2 * 2 + e;
                    float pi = acc[0][s][ci] + bs[j];
                    float pf = acc[1][s][ci] + bs[128 + j];
                    float pg = acc[2][s][ci] + bs[256 + j];
                    float po = acc[3][s][ci] + bs[384 + j];
                    float iv = 1.f / (1.f + expf(-pi));
                    float fv = 1.f / (1.f + expf(-pf));
                    float gv = tanhf(pg);
                    float ov = 1.f / (1.f + expf(-po));
                    float cp = (t == 0) ? 0.f : Cs[rl * 132 + j];
                    float cc = fmaf(fv, cp, iv * gv);
                    Cs[rl * 132 + j] = cc;
                    float hh = ov * tanhf(cc);
                    if (t < 3) As[(4 + (j >> 4)) * 1280 + rl * 20 + (j & 15)] = hh;
                    else       Bs[rl * 132 + j] = hh;   // stage (B bufs idle at t=3)
                }
            }

        if (t == 3) {
            __syncthreads();
            const int r = tid >> 3, j0 = (tid & 7) * 16;
#pragma unroll
            for (int v = 0; v < 4; v++) {
                float4 val = *(const float4*)&Bs[r * 132 + j0 + v * 4];
                *(float4*)&g_H[(size_t)(row0 + r) * HID + j0 + v * 4] = val;
            }
        }
        // t<3: next iteration's loop-top __syncthreads orders epilogue writes vs mma reads
    }
}

// ---------------- head: masked mean pool, 2-layer MLP, softmax probs ----------------
__global__ void __launch_bounds__(128) head_kernel(
        const int* __restrict__ mask,
        const float* __restrict__ W1, const float* __restrict__ b1,
        const float* __restrict__ W2, const float* __restrict__ b2,
        const float* __restrict__ Wp, const float* __restrict__ bp,
        float* __restrict__ out) {
    __shared__ float hf[4][2*HID];
    __shared__ float hid[4][HID];
    __shared__ float lg[4][3];

    const int j  = threadIdx.x;
    const int b0 = blockIdx.x * 4;

#pragma unroll
    for (int r = 0; r < 4; r++) {
        int b = b0 + r;
        hf[r][j] = g_H[(size_t)b * HID + j];
        float s = 0.f, cnt = 0.f;
#pragma unroll
        for (int n = 0; n < NMAX; n++) {
            float m = (float)mask[b * NMAX + n];
            s   = fmaf(m, g_H[(size_t)(BATCH + b * NMAX + n) * HID + j], s);
            cnt += m;
        }
        hf[r][HID + j] = s / fmaxf(cnt, 1.f);
    }
    __syncthreads();

    {
        float a0 = b1[j], a1 = a0, a2 = a0, a3 = a0;
        for (int k = 0; k < 2*HID; k++) {
            float w = W1[j * 2*HID + k];
            a0 = fmaf(w, hf[0][k], a0);
            a1 = fmaf(w, hf[1][k], a1);
            a2 = fmaf(w, hf[2][k], a2);
            a3 = fmaf(w, hf[3][k], a3);
        }
        hid[0][j] = fmaxf(a0, 0.f); hid[1][j] = fmaxf(a1, 0.f);
        hid[2][j] = fmaxf(a2, 0.f); hid[3][j] = fmaxf(a3, 0.f);
    }
    __syncthreads();

    for (int idx = j; idx < 4 * 36; idx += 128) {
        int r = idx / 36, o = idx % 36;
        float a = b2[o];
        for (int k = 0; k < HID; k++) a = fmaf(W2[o * HID + k], hid[r][k], a);
        out[(size_t)(b0 + r) * 36 + o] = a;
    }
    if (j < 12) {
        int r = j / 3, kk = j % 3;
        float a = bp[kk];
        for (int k = 0; k < 2*HID; k++) a = fmaf(Wp[kk * 2*HID + k], hf[r][k], a);
        lg[r][kk] = a;
    }
    __syncthreads();
    if (j < 12) {
        int r = j / 3, kk = j % 3;
        float m  = fmaxf(lg[r][0], fmaxf(lg[r][1], lg[r][2]));
        float e0 = expf(lg[r][0] - m), e1 = expf(lg[r][1] - m), e2 = expf(lg[r][2] - m);
        float e  = (kk == 0) ? e0 : ((kk == 1) ? e1 : e2);
        out[(size_t)BATCH * 36 + (size_t)(b0 + r) * 3 + kk] = e / (e0 + e1 + e2);
    }
}

// ---------------- launch ----------------
extern "C" void kernel_launch(void* const* d_in, const int* in_sizes, int n_in,
                              void* d_out, int out_size) {
    const float* x    = (const float*)d_in[0];
    const float* nb   = (const float*)d_in[1];
    const int*   mask = (const int*)  d_in[2];
    const float* We   = (const float*)d_in[3];
    const float* be   = (const float*)d_in[4];
    const float* Wih  = (const float*)d_in[5];
    const float* Whh  = (const float*)d_in[6];
    const float* bih  = (const float*)d_in[7];
    const float* bhh  = (const float*)d_in[8];
    const float* W1   = (const float*)d_in[9];
    const float* b1   = (const float*)d_in[10];
    const float* W2   = (const float*)d_in[11];
    const float* b2   = (const float*)d_in[12];
    const float* Wp   = (const float*)d_in[13];
    const float* bp   = (const float*)d_in[14];
    float* out = (float*)d_out;

    cudaFuncSetAttribute(lstm_fused_kernel, cudaFuncAttributeMaxDynamicSharedMemorySize, SMEM_BYTES);

    prep_kernel<<<(G4 * 192 + 255) / 256, 256>>>(Wih, Whh, bih, bhh);

    long total = (long)NSEQ * TSTEPS * DEMB;
    embed_kernel<<<(unsigned)((total + 255) / 256), 256>>>(x, nb, We, be);

    lstm_fused_kernel<<<NSEQ / MTILE, 512, SMEM_BYTES>>>();

    head_kernel<<<BATCH / 4, 128>>>(mask, W1, b1, W2, b2, Wp, bp, out);
}

// round 7
// speedup vs baseline: 1.6586x; 1.4613x over previous
#include <cuda_runtime.h>
#include <math.h>
#include <stdint.h>

#define BATCH 8192
#define NMAX  16
#define TSTEPS 4
#define DIN   4
#define DEMB  64
#define HID   128
#define G4    512
#define NSEQ  (BATCH*(1+NMAX))     // 139264 sequences
#define MTILE 64                   // sequences per CTA

// ---------------- scratch (device globals: allocation-free) ----------------
__device__ float g_E[(size_t)NSEQ*TSTEPS*DEMB]; // embedded inputs [seq][t][64], fp32
__device__ float g_H[(size_t)NSEQ*HID];         // FINAL hidden state only (row-major)
__device__ float g_W[(size_t)G4*192];           // combined weights [n][k0..191], fp32
__device__ float g_bsum[G4];                    // b_ih + b_hh

// ---------------- smem layout (floats) ----------------
#define A_OFF 0
#define B_OFF 15360
#define C_OFF 35840
#define BS_OFF 44288
#define SMEM_FLOATS 44800
#define SMEM_BYTES (SMEM_FLOATS*4)   // 179200

__device__ __forceinline__ void cp16(void* sdst, const void* gsrc) {
    uint32_t sa = (uint32_t)__cvta_generic_to_shared(sdst);
    asm volatile("cp.async.cg.shared.global [%0], [%1], 16;" :: "r"(sa), "l"(gsrc));
}
#define CP_COMMIT() asm volatile("cp.async.commit_group;" ::: "memory")
#define CP_WAIT(N)  asm volatile("cp.async.wait_group %0;" :: "n"(N) : "memory")

// pack two f32 into bf16x2: lo -> low half, hi -> high half
__device__ __forceinline__ uint32_t pack_bf2(float lo, float hi) {
    uint32_t r;
    asm("cvt.rn.bf16x2.f32 %0, %1, %2;" : "=r"(r) : "f"(hi), "f"(lo));
    return r;
}
// split float2 (consecutive-k pair) into hi/lo bf16x2 parts
__device__ __forceinline__ void split_bf2(float2 v, uint32_t& h, uint32_t& l) {
    h = pack_bf2(v.x, v.y);
    float r0 = v.x - __uint_as_float(h << 16);
    float r1 = v.y - __uint_as_float(h & 0xFFFF0000u);
    l = pack_bf2(r0, r1);
}

#define MMA_BF16(D, A0,A1,A2,A3, B0,B1)                                        \
    asm volatile(                                                              \
        "mma.sync.aligned.m16n8k16.row.col.f32.bf16.bf16.f32 "                 \
        "{%0,%1,%2,%3},{%4,%5,%6,%7},{%8,%9},{%0,%1,%2,%3};"                   \
        : "+f"((D)[0]), "+f"((D)[1]), "+f"((D)[2]), "+f"((D)[3])               \
        : "r"(A0), "r"(A1), "r"(A2), "r"(A3), "r"(B0), "r"(B1))

// ---------------- prep: combine weights (fp32), combine biases ----------------
__global__ void prep_kernel(const float* __restrict__ Wih, const float* __restrict__ Whh,
                            const float* __restrict__ bih, const float* __restrict__ bhh) {
    int i = blockIdx.x * 256 + threadIdx.x;
    if (i < G4 * 192) {
        int n = i / 192, k = i % 192;
        g_W[i] = (k < DEMB) ? Wih[n * DEMB + k] : Whh[n * HID + (k - DEMB)];
    }
    if (i < G4) g_bsum[i] = bih[i] + bhh[i];
}

// ---------------- embed: relu(x @ We^T + be), fp32 ----------------
__global__ void embed_kernel(const float* __restrict__ x, const float* __restrict__ nb,
                             const float* __restrict__ We, const float* __restrict__ be) {
    int idx = blockIdx.x * blockDim.x + threadIdx.x;
    if (idx >= NSEQ * TSTEPS * DEMB) return;
    int j   = idx & 63;
    int st  = idx >> 6;
    int t   = st & 3;
    int seq = st >> 2;
    const float* src = (seq < BATCH) ? (x  + ((size_t)seq * TSTEPS + t) * DIN)
                                     : (nb + ((size_t)(seq - BATCH) * TSTEPS + t) * DIN);
    float v = be[j];
#pragma unroll
    for (int d = 0; d < 4; d++) v = fmaf(src[d], We[j*4 + d], v);
    g_E[idx] = fmaxf(v, 0.f);
}

// ---------------- persistent 3xBF16 mma.sync LSTM (m16n8k16) ----------------
// CTA: 512 threads = 4 (m) x 4 (n) warps. Tile M=64 seqs x N=512 gates, K streamed 16-wide.
// Operands fp32 in smem; bf16 hi/lo split in registers. 3 MMAs per logical mma:
// ah*bh + al*bh + ah*bl (drops al*bl ~2^-18) -> near-fp32 accuracy at 2x tf32-k8 rate.
__global__ void __launch_bounds__(512, 1)
lstm_fused_kernel() {
    extern __shared__ float sm[];
    float* As = sm + A_OFF;
    float* Bs = sm + B_OFF;
    float* Cs = sm + C_OFF;
    float* bs = sm + BS_OFF;

    const int tid  = threadIdx.x;
    const int lane = tid & 31, wid = tid >> 5;
    const int wm = wid & 3, wn = wid >> 2;
    const int g = lane >> 2, q = lane & 3;
    const int m0 = wm * 16;
    const int row0 = blockIdx.x * MTILE;

    bs[tid] = g_bsum[tid];

    auto load_E = [&](int t) {
#pragma unroll
        for (int i = 0; i < 2; i++) {
            int idx = tid + i * 512;
            int r = idx >> 4, k4 = idx & 15;          // k = k4*4
            cp16(&As[(k4 >> 2) * 1280 + r * 20 + (k4 & 3) * 4],
                 g_E + (((size_t)(row0 + r) * TSTEPS + t) * DEMB + k4 * 4));
        }
    };
    auto load_B = [&](int c, int buf) {
        const float* w = g_W + (size_t)tid * 192 + c * 16;
        float* dst = Bs + buf * 10240 + tid * 20;
#pragma unroll
        for (int k4 = 0; k4 < 4; k4++) cp16(dst + k4 * 4, w + k4 * 4);
    };

    load_E(0); CP_COMMIT();
    load_B(0, 0); CP_COMMIT();
    load_B(1, 1); CP_COMMIT();

    for (int t = 0; t < TSTEPS; t++) {
        const int nch = (t == 0) ? 4 : 12;
        float acc[4][4][4];
#pragma unroll
        for (int a = 0; a < 4; a++)
#pragma unroll
            for (int b = 0; b < 4; b++)
#pragma unroll
                for (int c = 0; c < 4; c++) acc[a][b][c] = 0.f;

        for (int c = 0; c < nch; c++) {
            if ((t == 0 || t == 3) && c == nch - 1) { CP_WAIT(0); } else { CP_WAIT(1); }
            __syncthreads();

            // ---- 3xBF16 mma over chunk c (K=16 per mma, single k-step) ----
            const float* Ac = As + c * 1280;
            const float* Bc = Bs + (c & 1) * 10240;
            {
                const float* ap = Ac + (m0 + g) * 20 + 2 * q;
                float2 a0f = *(const float2*)(ap);            // row g,   k 2q,2q+1
                float2 a1f = *(const float2*)(ap + 8 * 20);   // row g+8
                float2 a2f = *(const float2*)(ap + 8);        // row g,   k 2q+8,2q+9
                float2 a3f = *(const float2*)(ap + 8 * 20 + 8);
                uint32_t ah0, al0, ah1, al1, ah2, al2, ah3, al3;
                split_bf2(a0f, ah0, al0);
                split_bf2(a1f, ah1, al1);
                split_bf2(a2f, ah2, al2);
                split_bf2(a3f, ah3, al3);
#pragma unroll
                for (int gate = 0; gate < 4; gate++)
#pragma unroll
                    for (int s = 0; s < 4; s++) {
                        const float* bp = Bc + (gate * 128 + wn * 32 + s * 8 + g) * 20 + 2 * q;
                        float2 b0f = *(const float2*)(bp);        // k 2q,2q+1
                        float2 b1f = *(const float2*)(bp + 8);    // k 2q+8,2q+9
                        uint32_t bh0, bl0, bh1, bl1;
                        split_bf2(b0f, bh0, bl0);
                        split_bf2(b1f, bh1, bl1);
                        float* d = acc[gate][s];
                        MMA_BF16(d, ah0, ah1, ah2, ah3, bh0, bh1);
                        MMA_BF16(d, al0, al1, al2, al3, bh0, bh1);
                        MMA_BF16(d, ah0, ah1, ah2, ah3, bl0, bl1);
                    }
            }
            __syncthreads();

            // ---- prefetch schedule (race-free) ----
            if (c + 2 < nch)                          { load_B(c + 2, c & 1); CP_COMMIT(); }
            else if (c == nch - 2 && t >= 1 && t < 3) { load_E(t + 1); CP_COMMIT(); }
            else if (c == nch - 1 && t < 3) {
                if (t == 0) { load_E(1); CP_COMMIT(); }
                load_B(0, 0); CP_COMMIT();
                load_B(1, 1); CP_COMMIT();
            }
        }

        // ---- register epilogue: gates -> c,h ----
#pragma unroll
        for (int s = 0; s < 4; s++)
#pragma unroll
            for (int h2 = 0; h2 < 2; h2++) {
                const int rl = m0 + g + h2 * 8;
#pragma unroll
                for (int e = 0; e < 2; e++) {
                    const int j  = wn * 32 + s * 8 + 2 * q + e;
                    const int ci = h2 * 2 + e;
                    float pi = acc[0][s][ci] + bs[j];
                    float pf = acc[1][s][ci] + bs[128 + j];
                    float pg = acc[2][s][ci] + bs[256 + j];
                    float po = acc[3][s][ci] + bs[384 + j];
                    float iv = 1.f / (1.f + expf(-pi));
                    float fv = 1.f / (1.f + expf(-pf));
                    float gv = tanhf(pg);
                    float ov = 1.f / (1.f + expf(-po));
                    float cp = (t == 0) ? 0.f : Cs[rl * 132 + j];
                    float cc = fmaf(fv, cp, iv * gv);
                    Cs[rl * 132 + j] = cc;
                    float hh = ov * tanhf(cc);
                    if (t < 3) As[(4 + (j >> 4)) * 1280 + rl * 20 + (j & 15)] = hh;
                    else       Bs[rl * 132 + j] = hh;
                }
            }

        if (t == 3) {
            __syncthreads();
            const int r = tid >> 3, j0 = (tid & 7) * 16;
#pragma unroll
            for (int v = 0; v < 4; v++) {
                float4 val = *(const float4*)&Bs[r * 132 + j0 + v * 4];
                *(float4*)&g_H[(size_t)(row0 + r) * HID + j0 + v * 4] = val;
            }
        }
    }
}

// ---------------- head v2: 32 rows/block, 256 threads, float4 everywhere ----------------
// dynamic smem: hf[32][256] (8192 f), hid[32][128] (4096 f), lg[32][4] (128 f)
#define H_HF   0
#define H_HID  8192
#define H_LG   12288
#define H_SMEM_FLOATS 12416
#define H_SMEM_BYTES (H_SMEM_FLOATS*4)   // 49664

__global__ void __launch_bounds__(256) head_kernel(
        const int* __restrict__ mask,
        const float* __restrict__ W1, const float* __restrict__ b1,
        const float* __restrict__ W2, const float* __restrict__ b2,
        const float* __restrict__ Wp, const float* __restrict__ bp,
        float* __restrict__ out) {
    extern __shared__ float hs[];
    float* hf  = hs + H_HF;    // [32][256]
    float* hid = hs + H_HID;   // [32][128]
    float* lg  = hs + H_LG;    // [32][4]

    const int tid = threadIdx.x;
    const int j   = tid & 127, rh = tid >> 7;   // rh in {0,1}: row half
    const int b0  = blockIdx.x * 32;

    // ---- pooling: hf[r] = [h_target | masked-mean neighbor h] ----
    for (int r16 = 0; r16 < 16; r16++) {
        int r = rh * 16 + r16, b = b0 + r;
        hf[r * 256 + j] = g_H[(size_t)b * HID + j];
        float s = 0.f, cnt = 0.f;
#pragma unroll
        for (int n = 0; n < NMAX; n++) {
            float m = (float)mask[b * NMAX + n];
            s   = fmaf(m, g_H[(size_t)(BATCH + b * NMAX + n) * HID + j], s);
            cnt += m;
        }
        hf[r * 256 + 128 + j] = s / fmaxf(cnt, 1.f);
    }
    __syncthreads();

    // ---- MLP1: hidden = relu(hf @ W1^T + b1); 16 rows per thread ----
    {
        float acc[16];
        float bj = b1[j];
#pragma unroll
        for (int r = 0; r < 16; r++) acc[r] = bj;
        for (int k4 = 0; k4 < 64; k4++) {
            float4 w = *(const float4*)&W1[(size_t)j * 256 + k4 * 4];
#pragma unroll
            for (int r16 = 0; r16 < 16; r16++) {
                float4 h4 = *(const float4*)&hf[(rh * 16 + r16) * 256 + k4 * 4];
                acc[r16] = fmaf(w.x, h4.x, fmaf(w.y, h4.y, fmaf(w.z, h4.z, fmaf(w.w, h4.w, acc[r16]))));
            }
        }
#pragma unroll
        for (int r16 = 0; r16 < 16; r16++)
            hid[(rh * 16 + r16) * 128 + j] = fmaxf(acc[r16], 0.f);
    }
    __syncthreads();

    // ---- traj = hid @ W2^T + b2 -> out[0 .. B*36) ----
    for (int idx = tid; idx < 32 * 36; idx += 256) {
        int r = idx / 36, o = idx % 36;
        float a = b2[o];
        for (int k4 = 0; k4 < 32; k4++) {
            float4 w  = *(const float4*)&W2[(size_t)o * 128 + k4 * 4];
            float4 h4 = *(const float4*)&hid[r * 128 + k4 * 4];
            a = fmaf(w.x, h4.x, fmaf(w.y, h4.y, fmaf(w.z, h4.z, fmaf(w.w, h4.w, a))));
        }
        out[(size_t)(b0 + r) * 36 + o] = a;
    }
    // ---- probs: softmax over K=3 ----
    if (tid < 96) {
        int r = tid / 3, kk = tid % 3;
        float a = bp[kk];
        for (int k4 = 0; k4 < 64; k4++) {
            float4 w  = *(const float4*)&Wp[(size_t)kk * 256 + k4 * 4];
            float4 h4 = *(const float4*)&hf[r * 256 + k4 * 4];
            a = fmaf(w.x, h4.x, fmaf(w.y, h4.y, fmaf(w.z, h4.z, fmaf(w.w, h4.w, a))));
        }
        lg[r * 4 + kk] = a;
    }
    __syncthreads();
    if (tid < 96) {
        int r = tid / 3, kk = tid % 3;
        float m  = fmaxf(lg[r * 4], fmaxf(lg[r * 4 + 1], lg[r * 4 + 2]));
        float e0 = expf(lg[r * 4] - m), e1 = expf(lg[r * 4 + 1] - m), e2 = expf(lg[r * 4 + 2] - m);
        float e  = (kk == 0) ? e0 : ((kk == 1) ? e1 : e2);
        out[(size_t)BATCH * 36 + (size_t)(b0 + r) * 3 + kk] = e / (e0 + e1 + e2);
    }
}

// ---------------- launch ----------------
extern "C" void kernel_launch(void* const* d_in, const int* in_sizes, int n_in,
                              void* d_out, int out_size) {
    const float* x    = (const float*)d_in[0];
    const float* nb   = (const float*)d_in[1];
    const int*   mask = (const int*)  d_in[2];
    const float* We   = (const float*)d_in[3];
    const float* be   = (const float*)d_in[4];
    const float* Wih  = (const float*)d_in[5];
    const float* Whh  = (const float*)d_in[6];
    const float* bih  = (const float*)d_in[7];
    const float* bhh  = (const float*)d_in[8];
    const float* W1   = (const float*)d_in[9];
    const float* b1   = (const float*)d_in[10];
    const float* W2   = (const float*)d_in[11];
    const float* b2   = (const float*)d_in[12];
    const float* Wp   = (const float*)d_in[13];
    const float* bp   = (const float*)d_in[14];
    float* out = (float*)d_out;

    cudaFuncSetAttribute(lstm_fused_kernel, cudaFuncAttributeMaxDynamicSharedMemorySize, SMEM_BYTES);
    cudaFuncSetAttribute(head_kernel, cudaFuncAttributeMaxDynamicSharedMemorySize, H_SMEM_BYTES);

    prep_kernel<<<(G4 * 192 + 255) / 256, 256>>>(Wih, Whh, bih, bhh);

    long total = (long)NSEQ * TSTEPS * DEMB;
    embed_kernel<<<(unsigned)((total + 255) / 256), 256>>>(x, nb, We, be);

    lstm_fused_kernel<<<NSEQ / MTILE, 512, SMEM_BYTES>>>();

    head_kernel<<<BATCH / 32, 256, H_SMEM_BYTES>>>(mask, W1, b1, W2, b2, Wp, bp, out);
}

// round 8
// speedup vs baseline: 2.5642x; 1.5460x over previous
#include <cuda_runtime.h>
#include <math.h>
#include <stdint.h>

#define BATCH 8192
#define NMAX  16
#define TSTEPS 4
#define DIN   4
#define DEMB  64
#define HID   128
#define G4    512
#define NSEQ  (BATCH*(1+NMAX))     // 139264 sequences
#define MTILE 64                   // sequences per CTA

// ---------------- scratch (device globals: allocation-free) ----------------
// E in bf16 hi/lo, k-permuted pairs: [seq*T][ch(4)][part(2)][8 words]
__device__ uint32_t g_Ebf[(size_t)NSEQ*TSTEPS*64];
__device__ float    g_H[(size_t)NSEQ*HID];      // FINAL hidden state
// weights bf16 hi/lo, permuted: [chunk(12)][part(2)][n(512)][8 words]
__device__ uint32_t g_Wbf[12*2*512*8];
__device__ float    g_bsum[G4];

// ---------------- smem layout (4-byte words) ----------------
// A: 12 chunks x 2 parts x 64 rows x 8 words = 12288
// B: 2 bufs x (2 parts x 512 n x 8 words)    = 16384
// C: [64][132] floats                         = 8448
// bias: 512
#define A_OFF  0
#define B_OFF  12288
#define C_OFF  28672
#define BS_OFF 37120
#define SMEM_WORDS 37632
#define SMEM_BYTES (SMEM_WORDS*4)   // 150528

__device__ __forceinline__ void cp16(void* sdst, const void* gsrc) {
    uint32_t sa = (uint32_t)__cvta_generic_to_shared(sdst);
    asm volatile("cp.async.cg.shared.global [%0], [%1], 16;" :: "r"(sa), "l"(gsrc));
}
#define CP_COMMIT() asm volatile("cp.async.commit_group;" ::: "memory")
#define CP_WAIT(N)  asm volatile("cp.async.wait_group %0;" :: "n"(N) : "memory")

// pack two f32 into bf16x2 (v0 -> low half = first k elem)
__device__ __forceinline__ uint32_t pack_bf2(float v0, float v1) {
    uint32_t r;
    asm("cvt.rn.bf16x2.f32 %0, %1, %2;" : "=r"(r) : "f"(v1), "f"(v0));
    return r;
}
// split consecutive-k f32 pair into hi/lo bf16x2
__device__ __forceinline__ void split2(float v0, float v1, uint32_t& h, uint32_t& l) {
    h = pack_bf2(v0, v1);
    float r0 = v0 - __uint_as_float(h << 16);
    float r1 = v1 - __uint_as_float(h & 0xFFFF0000u);
    l = pack_bf2(r0, r1);
}

#define MMA_BF16(D, A0,A1,A2,A3, B0,B1)                                        \
    asm volatile(                                                              \
        "mma.sync.aligned.m16n8k16.row.col.f32.bf16.bf16.f32 "                 \
        "{%0,%1,%2,%3},{%4,%5,%6,%7},{%8,%9},{%0,%1,%2,%3};"                   \
        : "+f"((D)[0]), "+f"((D)[1]), "+f"((D)[2]), "+f"((D)[3])               \
        : "r"(A0), "r"(A1), "r"(A2), "r"(A3), "r"(B0), "r"(B1))

// permuted word -> k pair: word w holds pair pp = (w&1) ? 4+(w>>1) : (w>>1)
// => thread q's 64-bit load at word 2q yields k(2q,2q+1) and k(2q+8,2q+9).

// ---------------- prep: split weights to bf16 hi/lo permuted layout ----------------
__global__ void prep_kernel(const float* __restrict__ Wih, const float* __restrict__ Whh,
                            const float* __restrict__ bih, const float* __restrict__ bhh) {
    int i = blockIdx.x * 256 + threadIdx.x;
    if (i < 12 * 512 * 8) {
        int w = i & 7, n = (i >> 3) & 511, c = i >> 12;
        int pp = (w & 1) ? 4 + (w >> 1) : (w >> 1);
        int k = c * 16 + 2 * pp;
        float v0, v1;
        if (k < DEMB) { v0 = Wih[n * DEMB + k];        v1 = Wih[n * DEMB + k + 1]; }
        else          { v0 = Whh[n * HID + (k - 64)];  v1 = Whh[n * HID + (k - 63)]; }
        uint32_t h, l;
        split2(v0, v1, h, l);
        g_Wbf[(c * 2 + 0) * 4096 + n * 8 + w] = h;
        g_Wbf[(c * 2 + 1) * 4096 + n * 8 + w] = l;
    }
    if (i < G4) g_bsum[i] = bih[i] + bhh[i];
}

// ---------------- embed: relu(x @ We^T + be) -> bf16 hi/lo permuted ----------------
__global__ void embed_kernel(const float* __restrict__ x, const float* __restrict__ nb,
                             const float* __restrict__ We, const float* __restrict__ be) {
    int idx = blockIdx.x * blockDim.x + threadIdx.x;
    if (idx >= NSEQ * TSTEPS * 32) return;
    int widx = idx & 31;
    int st   = idx >> 5;          // seq*T + t
    int seq  = st >> 2;
    int ch = widx >> 3, w = widx & 7;
    int pp = (w & 1) ? 4 + (w >> 1) : (w >> 1);
    int j  = ch * 16 + 2 * pp;    // embed dims j, j+1
    const float* src = (seq < BATCH) ? (x  + (size_t)st * DIN)
                                     : (nb + ((size_t)(seq - BATCH) * TSTEPS + (st & 3)) * DIN);
    float v0 = be[j], v1 = be[j + 1];
#pragma unroll
    for (int d = 0; d < 4; d++) {
        float s = src[d];
        v0 = fmaf(s, We[j * 4 + d], v0);
        v1 = fmaf(s, We[(j + 1) * 4 + d], v1);
    }
    v0 = fmaxf(v0, 0.f); v1 = fmaxf(v1, 0.f);
    uint32_t h, l;
    split2(v0, v1, h, l);
    size_t base = (size_t)st * 64 + ch * 16 + w;
    g_Ebf[base]     = h;
    g_Ebf[base + 8] = l;
}

// ---------------- persistent 3xBF16 mma.sync LSTM, pre-split operands ----------------
// CTA: 512 threads = 4 (m) x 4 (n) warps. M=64 seqs x N=512 gates, K chunks of 16.
// All bf16 hi/lo splits precomputed; mainloop = LDS.64 fragment loads + MMAs only.
__global__ void __launch_bounds__(512, 1)
lstm_fused_kernel() {
    extern __shared__ uint32_t smw[];
    uint32_t* Asw = smw + A_OFF;
    uint32_t* Bsw = smw + B_OFF;
    float*    Cs  = (float*)(smw + C_OFF);
    float*    bs  = (float*)(smw + BS_OFF);

    const int tid  = threadIdx.x;
    const int lane = tid & 31, wid = tid >> 5;
    const int wm = wid & 3, wn = wid >> 2;
    const int g = lane >> 2, q = lane & 3;
    const int m0 = wm * 16;
    const int row0 = blockIdx.x * MTILE;

    bs[tid] = g_bsum[tid];

    // E loader: 64 rows x 4 chunks x 2 parts x 8 words = 1024 x 16B segments
    auto load_E = [&](int t) {
#pragma unroll
        for (int i = 0; i < 2; i++) {
            int idx = tid + i * 512;
            int r = idx >> 4, sr = idx & 15;
            int ch = sr >> 2, part = (sr >> 1) & 1, w4 = (sr & 1) * 4;
            cp16(Asw + ((ch * 2 + part) * 64 + r) * 8 + w4,
                 g_Ebf + ((size_t)(row0 + r) * TSTEPS + t) * 64 + ch * 16 + part * 8 + w4);
        }
    };
    // B loader: flat 8192-word chunk copy (2048 x 16B segments)
    auto load_B = [&](int c, int buf) {
#pragma unroll
        for (int i = 0; i < 4; i++) {
            int idx = tid + i * 512;
            cp16(Bsw + buf * 8192 + idx * 4, g_Wbf + c * 8192 + idx * 4);
        }
    };

    load_E(0); CP_COMMIT();
    load_B(0, 0); CP_COMMIT();
    load_B(1, 1); CP_COMMIT();

    for (int t = 0; t < TSTEPS; t++) {
        const int nch = (t == 0) ? 4 : 12;
        float acc[4][4][4];
#pragma unroll
        for (int a = 0; a < 4; a++)
#pragma unroll
            for (int b = 0; b < 4; b++)
#pragma unroll
                for (int c = 0; c < 4; c++) acc[a][b][c] = 0.f;

        for (int c = 0; c < nch; c++) {
            if ((t == 0 || t == 3) && c == nch - 1) { CP_WAIT(0); } else { CP_WAIT(1); }
            __syncthreads();

            // ---- fragment loads (all pre-split bf16) ----
            const uint32_t* Ach = Asw + (c * 2) * 512;   // part stride = 512 words
            uint2 ahA = *(const uint2*)(Ach + (m0 + g) * 8 + 2 * q);         // a0,a2 hi
            uint2 ahB = *(const uint2*)(Ach + (m0 + g + 8) * 8 + 2 * q);     // a1,a3 hi
            uint2 alA = *(const uint2*)(Ach + 512 + (m0 + g) * 8 + 2 * q);   // lo
            uint2 alB = *(const uint2*)(Ach + 512 + (m0 + g + 8) * 8 + 2 * q);
            const uint32_t* Bh = Bsw + (c & 1) * 8192;
            const uint32_t* Bl = Bh + 4096;
#pragma unroll
            for (int gate = 0; gate < 4; gate++)
#pragma unroll
                for (int s = 0; s < 4; s++) {
                    int n = gate * 128 + wn * 32 + s * 8 + g;
                    uint2 bh = *(const uint2*)(Bh + n * 8 + 2 * q);
                    uint2 bl = *(const uint2*)(Bl + n * 8 + 2 * q);
                    float* d = acc[gate][s];
                    MMA_BF16(d, ahA.x, ahB.x, ahA.y, ahB.y, bh.x, bh.y);
                    MMA_BF16(d, alA.x, alB.x, alA.y, alB.y, bh.x, bh.y);
                    MMA_BF16(d, ahA.x, ahB.x, ahA.y, ahB.y, bl.x, bl.y);
                }
            __syncthreads();

            // ---- prefetch schedule (race-free; validated round 6) ----
            if (c + 2 < nch)                          { load_B(c + 2, c & 1); CP_COMMIT(); }
            else if (c == nch - 2 && t >= 1 && t < 3) { load_E(t + 1); CP_COMMIT(); }
            else if (c == nch - 1 && t < 3) {
                if (t == 0) { load_E(1); CP_COMMIT(); }
                load_B(0, 0); CP_COMMIT();
                load_B(1, 1); CP_COMMIT();
            }
        }

        // ---- register epilogue: gates -> c,h; h split to bf16 in A slots ----
#pragma unroll
        for (int s = 0; s < 4; s++)
#pragma unroll
            for (int h2 = 0; h2 < 2; h2++) {
                const int rl = m0 + g + h2 * 8;
                const int j0 = wn * 32 + s * 8 + 2 * q;   // even pair (j0, j0+1)
                float hh[2];
#pragma unroll
                for (int e = 0; e < 2; e++) {
                    const int j  = j0 + e;
                    const int ci = h2 * 2 + e;
                    float pi = acc[0][s][ci] + bs[j];
                    float pf = acc[1][s][ci] + bs[128 + j];
                    float pg = acc[2][s][ci] + bs[256 + j];
                    float po = acc[3][s][ci] + bs[384 + j];
                    float iv = 1.f / (1.f + expf(-pi));
                    float fv = 1.f / (1.f + expf(-pf));
                    float gv = tanhf(pg);
                    float ov = 1.f / (1.f + expf(-po));
                    float cp = (t == 0) ? 0.f : Cs[rl * 132 + j];
                    float cc = fmaf(fv, cp, iv * gv);
                    Cs[rl * 132 + j] = cc;
                    hh[e] = ov * tanhf(cc);
                }
                if (t < 3) {
                    const int ch = 4 + (j0 >> 4);
                    const int lp = (j0 & 15) >> 1;
                    const int w  = (lp < 4) ? 2 * lp : 2 * (lp - 4) + 1;
                    uint32_t h, l;
                    split2(hh[0], hh[1], h, l);
                    Asw[(ch * 2 + 0) * 512 + rl * 8 + w] = h;
                    Asw[(ch * 2 + 1) * 512 + rl * 8 + w] = l;
                } else {
                    float* stage = (float*)Bsw;
                    stage[rl * 132 + j0]     = hh[0];
                    stage[rl * 132 + j0 + 1] = hh[1];
                }
            }

        if (t == 3) {
            __syncthreads();
            const float* stage = (const float*)Bsw;
            const int r = tid >> 3, j0 = (tid & 7) * 16;
#pragma unroll
            for (int v = 0; v < 4; v++) {
                float4 val = *(const float4*)&stage[r * 132 + j0 + v * 4];
                *(float4*)&g_H[(size_t)(row0 + r) * HID + j0 + v * 4] = val;
            }
        }
    }
}

// ---------------- head v3: 16 rows/block (2x grid for occupancy) ----------------
#define H_HF   0
#define H_HID  4096
#define H_LG   6144
#define H_SMEM_FLOATS 6208
#define H_SMEM_BYTES (H_SMEM_FLOATS*4)

__global__ void __launch_bounds__(256) head_kernel(
        const int* __restrict__ mask,
        const float* __restrict__ W1, const float* __restrict__ b1,
        const float* __restrict__ W2, const float* __restrict__ b2,
        const float* __restrict__ Wp, const float* __restrict__ bp,
        float* __restrict__ out) {
    extern __shared__ float hs[];
    float* hf  = hs + H_HF;    // [16][256]
    float* hid = hs + H_HID;   // [16][128]
    float* lg  = hs + H_LG;    // [16][4]

    const int tid = threadIdx.x;
    const int j   = tid & 127, rh = tid >> 7;   // row half: rows rh*8 .. rh*8+7
    const int b0  = blockIdx.x * 16;

#pragma unroll
    for (int r8 = 0; r8 < 8; r8++) {
        int r = rh * 8 + r8, b = b0 + r;
        hf[r * 256 + j] = g_H[(size_t)b * HID + j];
        float s = 0.f, cnt = 0.f;
#pragma unroll
        for (int n = 0; n < NMAX; n++) {
            float m = (float)mask[b * NMAX + n];
            s   = fmaf(m, g_H[(size_t)(BATCH + b * NMAX + n) * HID + j], s);
            cnt += m;
        }
        hf[r * 256 + 128 + j] = s / fmaxf(cnt, 1.f);
    }
    __syncthreads();

    {
        float acc[8];
        float bj = b1[j];
#pragma unroll
        for (int r = 0; r < 8; r++) acc[r] = bj;
        for (int k4 = 0; k4 < 64; k4++) {
            float4 w = *(const float4*)&W1[(size_t)j * 256 + k4 * 4];
#pragma unroll
            for (int r8 = 0; r8 < 8; r8++) {
                float4 h4 = *(const float4*)&hf[(rh * 8 + r8) * 256 + k4 * 4];
                acc[r8] = fmaf(w.x, h4.x, fmaf(w.y, h4.y, fmaf(w.z, h4.z, fmaf(w.w, h4.w, acc[r8]))));
            }
        }
#pragma unroll
        for (int r8 = 0; r8 < 8; r8++)
            hid[(rh * 8 + r8) * 128 + j] = fmaxf(acc[r8], 0.f);
    }
    __syncthreads();

    for (int idx = tid; idx < 16 * 36; idx += 256) {
        int r = idx / 36, o = idx % 36;
        float a = b2[o];
        for (int k4 = 0; k4 < 32; k4++) {
            float4 w  = *(const float4*)&W2[(size_t)o * 128 + k4 * 4];
            float4 h4 = *(const float4*)&hid[r * 128 + k4 * 4];
            a = fmaf(w.x, h4.x, fmaf(w.y, h4.y, fmaf(w.z, h4.z, fmaf(w.w, h4.w, a))));
        }
        out[(size_t)(b0 + r) * 36 + o] = a;
    }
    if (tid < 48) {
        int r = tid / 3, kk = tid % 3;
        float a = bp[kk];
        for (int k4 = 0; k4 < 64; k4++) {
            float4 w  = *(const float4*)&Wp[(size_t)kk * 256 + k4 * 4];
            float4 h4 = *(const float4*)&hf[r * 256 + k4 * 4];
            a = fmaf(w.x, h4.x, fmaf(w.y, h4.y, fmaf(w.z, h4.z, fmaf(w.w, h4.w, a))));
        }
        lg[r * 4 + kk] = a;
    }
    __syncthreads();
    if (tid < 48) {
        int r = tid / 3, kk = tid % 3;
        float m  = fmaxf(lg[r * 4], fmaxf(lg[r * 4 + 1], lg[r * 4 + 2]));
        float e0 = expf(lg[r * 4] - m), e1 = expf(lg[r * 4 + 1] - m), e2 = expf(lg[r * 4 + 2] - m);
        float e  = (kk == 0) ? e0 : ((kk == 1) ? e1 : e2);
        out[(size_t)BATCH * 36 + (size_t)(b0 + r) * 3 + kk] = e / (e0 + e1 + e2);
    }
}

// ---------------- launch ----------------
extern "C" void kernel_launch(void* const* d_in, const int* in_sizes, int n_in,
                              void* d_out, int out_size) {
    const float* x    = (const float*)d_in[0];
    const float* nb   = (const float*)d_in[1];
    const int*   mask = (const int*)  d_in[2];
    const float* We   = (const float*)d_in[3];
    const float* be   = (const float*)d_in[4];
    const float* Wih  = (const float*)d_in[5];
    const float* Whh  = (const float*)d_in[6];
    const float* bih  = (const float*)d_in[7];
    const float* bhh  = (const float*)d_in[8];
    const float* W1   = (const float*)d_in[9];
    const float* b1   = (const float*)d_in[10];
    const float* W2   = (const float*)d_in[11];
    const float* b2   = (const float*)d_in[12];
    const float* Wp   = (const float*)d_in[13];
    const float* bp   = (const float*)d_in[14];
    float* out = (float*)d_out;

    cudaFuncSetAttribute(lstm_fused_kernel, cudaFuncAttributeMaxDynamicSharedMemorySize, SMEM_BYTES);
    cudaFuncSetAttribute(head_kernel, cudaFuncAttributeMaxDynamicSharedMemorySize, H_SMEM_BYTES);

    prep_kernel<<<(12 * 512 * 8 + 255) / 256, 256>>>(Wih, Whh, bih, bhh);

    long total = (long)NSEQ * TSTEPS * 32;
    embed_kernel<<<(unsigned)((total + 255) / 256), 256>>>(x, nb, We, be);

    lstm_fused_kernel<<<NSEQ / MTILE, 512, SMEM_BYTES>>>();

    head_kernel<<<BATCH / 16, 256, H_SMEM_BYTES>>>(mask, W1, b1, W2, b2, Wp, bp, out);
}

// round 9
// speedup vs baseline: 4.4095x; 1.7196x over previous
#include <cuda_runtime.h>
#include <math.h>
#include <stdint.h>

#define BATCH 8192
#define NMAX  16
#define TSTEPS 4
#define DIN   4
#define DEMB  64
#define HID   128
#define G4    512
#define NSEQ  (BATCH*(1+NMAX))     // 139264 sequences
#define MTILE 64                   // sequences per CTA

// ---------------- scratch (device globals: allocation-free) ----------------
__device__ float    g_H[(size_t)NSEQ*HID];      // final hidden; masked entries stay 0
__device__ uint32_t g_Wbf[12*2*512*8];          // weights bf16 hi/lo, permuted
__device__ float    g_bsum[G4];
__device__ int      g_cnt;                      // number of active sequences
__device__ int      g_active[NSEQ];             // compacted active ids (padded with 0)

// ---------------- smem layout (4-byte words) ----------------
// A: 12 chunks x 2 parts x 64 rows x 8 words = 12288
// B: 2 bufs x 8192                            = 16384
// C: [64][132] floats                          = 8448
// bias 512 | We 256 | be 64 | ids 64
#define A_OFF  0
#define B_OFF  12288
#define C_OFF  28672
#define BS_OFF 37120
#define WE_OFF 37632
#define BE_OFF 37888
#define ID_OFF 37952
#define SMEM_WORDS 38016
#define SMEM_BYTES (SMEM_WORDS*4)   // 152064

__device__ __forceinline__ void cp16(void* sdst, const void* gsrc) {
    uint32_t sa = (uint32_t)__cvta_generic_to_shared(sdst);
    asm volatile("cp.async.cg.shared.global [%0], [%1], 16;" :: "r"(sa), "l"(gsrc));
}
#define CP_COMMIT() asm volatile("cp.async.commit_group;" ::: "memory")
#define CP_WAIT(N)  asm volatile("cp.async.wait_group %0;" :: "n"(N) : "memory")

__device__ __forceinline__ uint32_t pack_bf2(float v0, float v1) {
    uint32_t r;
    asm("cvt.rn.bf16x2.f32 %0, %1, %2;" : "=r"(r) : "f"(v1), "f"(v0));
    return r;
}
__device__ __forceinline__ void split2(float v0, float v1, uint32_t& h, uint32_t& l) {
    h = pack_bf2(v0, v1);
    float r0 = v0 - __uint_as_float(h << 16);
    float r1 = v1 - __uint_as_float(h & 0xFFFF0000u);
    l = pack_bf2(r0, r1);
}

#define MMA_BF16(D, A0,A1,A2,A3, B0,B1)                                        \
    asm volatile(                                                              \
        "mma.sync.aligned.m16n8k16.row.col.f32.bf16.bf16.f32 "                 \
        "{%0,%1,%2,%3},{%4,%5,%6,%7},{%8,%9},{%0,%1,%2,%3};"                   \
        : "+f"((D)[0]), "+f"((D)[1]), "+f"((D)[2]), "+f"((D)[3])               \
        : "r"(A0), "r"(A1), "r"(A2), "r"(A3), "r"(B0), "r"(B1))

// ---------------- prep: split weights to bf16 hi/lo permuted layout ----------------
__global__ void prep_kernel(const float* __restrict__ Wih, const float* __restrict__ Whh,
                            const float* __restrict__ bih, const float* __restrict__ bhh) {
    int i = blockIdx.x * 256 + threadIdx.x;
    if (i < 12 * 512 * 8) {
        int w = i & 7, n = (i >> 3) & 511, c = i >> 12;
        int pp = (w & 1) ? 4 + (w >> 1) : (w >> 1);
        int k = c * 16 + 2 * pp;
        float v0, v1;
        if (k < DEMB) { v0 = Wih[n * DEMB + k];        v1 = Wih[n * DEMB + k + 1]; }
        else          { v0 = Whh[n * HID + (k - 64)];  v1 = Whh[n * HID + (k - 63)]; }
        uint32_t h, l;
        split2(v0, v1, h, l);
        g_Wbf[(c * 2 + 0) * 4096 + n * 8 + w] = h;
        g_Wbf[(c * 2 + 1) * 4096 + n * 8 + w] = l;
    }
    if (i < G4) g_bsum[i] = bih[i] + bhh[i];
}

// ---------------- compaction: active = targets + unmasked neighbors ----------------
__global__ void reset_kernel() { if (threadIdx.x == 0 && blockIdx.x == 0) g_cnt = 0; }

__global__ void append_kernel(const int* __restrict__ mask) {
    int i = blockIdx.x * 256 + threadIdx.x;
    bool act = false;
    if (i < NSEQ) act = (i < BATCH) || (mask[i - BATCH] != 0);
    unsigned bal = __ballot_sync(0xFFFFFFFFu, act);
    int lane = threadIdx.x & 31;
    int n = __popc(bal);
    int base = 0;
    if (lane == 0 && n) base = atomicAdd(&g_cnt, n);
    base = __shfl_sync(0xFFFFFFFFu, base, 0);
    if (act) g_active[base + __popc(bal & ((1u << lane) - 1))] = i;
}

__global__ void pad_kernel() {
    int i = blockIdx.x * 256 + threadIdx.x;
    if (i < NSEQ && i >= g_cnt) g_active[i] = 0;   // duplicate seq 0: benign idempotent work
}

// ---------------- persistent 3xBF16 LSTM with inline embed + compaction ----------------
__global__ void __launch_bounds__(512, 1)
lstm_fused_kernel(const float* __restrict__ x, const float* __restrict__ nb,
                  const float* __restrict__ We, const float* __restrict__ be) {
    if (blockIdx.x * MTILE >= g_cnt) return;       // fully-inactive CTA

    extern __shared__ uint32_t smw[];
    uint32_t* Asw = smw + A_OFF;
    uint32_t* Bsw = smw + B_OFF;
    float*    Cs  = (float*)(smw + C_OFF);
    float*    bs  = (float*)(smw + BS_OFF);
    float*    WeS = (float*)(smw + WE_OFF);
    float*    beS = (float*)(smw + BE_OFF);
    int*      ids = (int*)  (smw + ID_OFF);

    const int tid  = threadIdx.x;
    const int lane = tid & 31, wid = tid >> 5;
    const int wm = wid & 3, wn = wid >> 2;
    const int g = lane >> 2, q = lane & 3;
    const int m0 = wm * 16;
    const int row0 = blockIdx.x * MTILE;

    bs[tid] = g_bsum[tid];
    if (tid < 256) WeS[tid] = We[tid];
    if (tid < 64)  { beS[tid] = be[tid]; ids[tid] = g_active[row0 + tid]; }
    __syncthreads();

    // inline embed: E(t) for this CTA's 64 rows -> A chunks 0..3 (bf16 hi/lo permuted)
    auto compute_E = [&](int t) {
        const int row = tid >> 3, sub = tid & 7;
        const int id  = ids[row];
        const float* src = (id < BATCH)
            ? x  + ((size_t)id * TSTEPS + t) * DIN
            : nb + ((size_t)(id - BATCH) * TSTEPS + t) * DIN;
        float4 xv = *(const float4*)src;
#pragma unroll
        for (int ch = 0; ch < 4; ch++) {
            const int w  = sub;
            const int pp = (w & 1) ? 4 + (w >> 1) : (w >> 1);
            const int j  = ch * 16 + 2 * pp;
            float v0 = beS[j], v1 = beS[j + 1];
            v0 = fmaf(xv.x, WeS[j*4+0], v0); v0 = fmaf(xv.y, WeS[j*4+1], v0);
            v0 = fmaf(xv.z, WeS[j*4+2], v0); v0 = fmaf(xv.w, WeS[j*4+3], v0);
            v1 = fmaf(xv.x, WeS[(j+1)*4+0], v1); v1 = fmaf(xv.y, WeS[(j+1)*4+1], v1);
            v1 = fmaf(xv.z, WeS[(j+1)*4+2], v1); v1 = fmaf(xv.w, WeS[(j+1)*4+3], v1);
            v0 = fmaxf(v0, 0.f); v1 = fmaxf(v1, 0.f);
            uint32_t h, l;
            split2(v0, v1, h, l);
            Asw[(ch * 2 + 0) * 512 + row * 8 + w] = h;
            Asw[(ch * 2 + 1) * 512 + row * 8 + w] = l;
        }
    };
    auto load_B = [&](int c, int buf) {
#pragma unroll
        for (int i = 0; i < 4; i++) {
            int idx = tid + i * 512;
            cp16(Bsw + buf * 8192 + idx * 4, g_Wbf + c * 8192 + idx * 4);
        }
    };

    compute_E(0);
    load_B(0, 0); CP_COMMIT();
    load_B(1, 1); CP_COMMIT();

    for (int t = 0; t < TSTEPS; t++) {
        const int nch = (t == 0) ? 4 : 12;
        float acc[4][4][4];
#pragma unroll
        for (int a = 0; a < 4; a++)
#pragma unroll
            for (int b = 0; b < 4; b++)
#pragma unroll
                for (int c = 0; c < 4; c++) acc[a][b][c] = 0.f;

        for (int c = 0; c < nch; c++) {
            if (c == nch - 1) { CP_WAIT(0); } else { CP_WAIT(1); }
            __syncthreads();

            const uint32_t* Ach = Asw + (c * 2) * 512;
            uint2 ahA = *(const uint2*)(Ach + (m0 + g) * 8 + 2 * q);
            uint2 ahB = *(const uint2*)(Ach + (m0 + g + 8) * 8 + 2 * q);
            uint2 alA = *(const uint2*)(Ach + 512 + (m0 + g) * 8 + 2 * q);
            uint2 alB = *(const uint2*)(Ach + 512 + (m0 + g + 8) * 8 + 2 * q);
            const uint32_t* Bh = Bsw + (c & 1) * 8192;
            const uint32_t* Bl = Bh + 4096;
#pragma unroll
            for (int gate = 0; gate < 4; gate++)
#pragma unroll
                for (int s = 0; s < 4; s++) {
                    int n = gate * 128 + wn * 32 + s * 8 + g;
                    uint2 bh = *(const uint2*)(Bh + n * 8 + 2 * q);
                    uint2 bl = *(const uint2*)(Bl + n * 8 + 2 * q);
                    float* d = acc[gate][s];
                    MMA_BF16(d, ahA.x, ahB.x, ahA.y, ahB.y, bh.x, bh.y);
                    MMA_BF16(d, alA.x, alB.x, alA.y, alB.y, bh.x, bh.y);
                    MMA_BF16(d, ahA.x, ahB.x, ahA.y, ahB.y, bl.x, bl.y);
                }
            __syncthreads();

            // ---- prefetch / E-compute schedule (race-free) ----
            if (c + 2 < nch)                          { load_B(c + 2, c & 1); CP_COMMIT(); }
            else if (c == nch - 2 && t >= 1 && t < 3) { compute_E(t + 1); }
            else if (c == nch - 1 && t < 3) {
                if (t == 0) compute_E(1);             // chunk 0-3 reads done (post-sync)
                load_B(0, 0); CP_COMMIT();
                load_B(1, 1); CP_COMMIT();
            }
        }

        // ---- register epilogue: gates -> c,h; h split to bf16 into A slots ----
#pragma unroll
        for (int s = 0; s < 4; s++)
#pragma unroll
            for (int h2 = 0; h2 < 2; h2++) {
                const int rl = m0 + g + h2 * 8;
                const int j0 = wn * 32 + s * 8 + 2 * q;
                float hh[2];
#pragma unroll
                for (int e = 0; e < 2; e++) {
                    const int j  = j0 + e;
                    const int ci = h2 * 2 + e;
                    float pi = acc[0][s][ci] + bs[j];
                    float pf = acc[1][s][ci] + bs[128 + j];
                    float pg = acc[2][s][ci] + bs[256 + j];
                    float po = acc[3][s][ci] + bs[384 + j];
                    float iv = 1.f / (1.f + expf(-pi));
                    float fv = 1.f / (1.f + expf(-pf));
                    float gv = tanhf(pg);
                    float ov = 1.f / (1.f + expf(-po));
                    float cp = (t == 0) ? 0.f : Cs[rl * 132 + j];
                    float cc = fmaf(fv, cp, iv * gv);
                    Cs[rl * 132 + j] = cc;
                    hh[e] = ov * tanhf(cc);
                }
                if (t < 3) {
                    const int ch = 4 + (j0 >> 4);
                    const int lp = (j0 & 15) >> 1;
                    const int w  = (lp < 4) ? 2 * lp : 2 * (lp - 4) + 1;
                    uint32_t h, l;
                    split2(hh[0], hh[1], h, l);
                    Asw[(ch * 2 + 0) * 512 + rl * 8 + w] = h;
                    Asw[(ch * 2 + 1) * 512 + rl * 8 + w] = l;
                } else {
                    float* stage = (float*)Bsw;
                    stage[rl * 132 + j0]     = hh[0];
                    stage[rl * 132 + j0 + 1] = hh[1];
                }
            }

        if (t == 3) {
            __syncthreads();
            const float* stage = (const float*)Bsw;
            const int r = tid >> 3, j0 = (tid & 7) * 16;
            const size_t hb = (size_t)ids[r] * HID;
#pragma unroll
            for (int v = 0; v < 4; v++) {
                float4 val = *(const float4*)&stage[r * 132 + j0 + v * 4];
                *(float4*)&g_H[hb + j0 + v * 4] = val;
            }
        }
    }
}

// ---------------- head v4: 8 rows/block, masked loads skipped ----------------
#define H_HF   0
#define H_HID  2048
#define H_LG   3072
#define H_SMEM_FLOATS 3104
#define H_SMEM_BYTES (H_SMEM_FLOATS*4)

__global__ void __launch_bounds__(256) head_kernel(
        const int* __restrict__ mask,
        const float* __restrict__ W1, const float* __restrict__ b1,
        const float* __restrict__ W2, const float* __restrict__ b2,
        const float* __restrict__ Wp, const float* __restrict__ bp,
        float* __restrict__ out) {
    extern __shared__ float hs[];
    float* hf  = hs + H_HF;    // [8][256]
    float* hid = hs + H_HID;   // [8][128]
    float* lg  = hs + H_LG;    // [8][4]

    const int tid = threadIdx.x;
    const int j   = tid & 127, rh = tid >> 7;
    const int b0  = blockIdx.x * 8;

#pragma unroll
    for (int r4 = 0; r4 < 4; r4++) {
        int r = rh * 4 + r4, b = b0 + r;
        hf[r * 256 + j] = g_H[(size_t)b * HID + j];
        float s = 0.f, cnt = 0.f;
#pragma unroll
        for (int n = 0; n < NMAX; n++) {
            if (mask[b * NMAX + n] != 0) {
                s += g_H[(size_t)(BATCH + b * NMAX + n) * HID + j];
                cnt += 1.f;
            }
        }
        hf[r * 256 + 128 + j] = s / fmaxf(cnt, 1.f);
    }
    __syncthreads();

    {
        float acc[4];
        float bj = b1[j];
#pragma unroll
        for (int r = 0; r < 4; r++) acc[r] = bj;
        for (int k4 = 0; k4 < 64; k4++) {
            float4 w = *(const float4*)&W1[(size_t)j * 256 + k4 * 4];
#pragma unroll
            for (int r4 = 0; r4 < 4; r4++) {
                float4 h4 = *(const float4*)&hf[(rh * 4 + r4) * 256 + k4 * 4];
                acc[r4] = fmaf(w.x, h4.x, fmaf(w.y, h4.y, fmaf(w.z, h4.z, fmaf(w.w, h4.w, acc[r4]))));
            }
        }
#pragma unroll
        for (int r4 = 0; r4 < 4; r4++)
            hid[(rh * 4 + r4) * 128 + j] = fmaxf(acc[r4], 0.f);
    }
    __syncthreads();

    for (int idx = tid; idx < 8 * 36; idx += 256) {
        int r = idx / 36, o = idx % 36;
        float a = b2[o];
        for (int k4 = 0; k4 < 32; k4++) {
            float4 w  = *(const float4*)&W2[(size_t)o * 128 + k4 * 4];
            float4 h4 = *(const float4*)&hid[r * 128 + k4 * 4];
            a = fmaf(w.x, h4.x, fmaf(w.y, h4.y, fmaf(w.z, h4.z, fmaf(w.w, h4.w, a))));
        }
        out[(size_t)(b0 + r) * 36 + o] = a;
    }
    if (tid < 24) {
        int r = tid / 3, kk = tid % 3;
        float a = bp[kk];
        for (int k4 = 0; k4 < 64; k4++) {
            float4 w  = *(const float4*)&Wp[(size_t)kk * 256 + k4 * 4];
            float4 h4 = *(const float4*)&hf[r * 256 + k4 * 4];
            a = fmaf(w.x, h4.x, fmaf(w.y, h4.y, fmaf(w.z, h4.z, fmaf(w.w, h4.w, a))));
        }
        lg[r * 4 + kk] = a;
    }
    __syncthreads();
    if (tid < 24) {
        int r = tid / 3, kk = tid % 3;
        float m  = fmaxf(lg[r * 4], fmaxf(lg[r * 4 + 1], lg[r * 4 + 2]));
        float e0 = expf(lg[r * 4] - m), e1 = expf(lg[r * 4 + 1] - m), e2 = expf(lg[r * 4 + 2] - m);
        float e  = (kk == 0) ? e0 : ((kk == 1) ? e1 : e2);
        out[(size_t)BATCH * 36 + (size_t)(b0 + r) * 3 + kk] = e / (e0 + e1 + e2);
    }
}

// ---------------- launch ----------------
extern "C" void kernel_launch(void* const* d_in, const int* in_sizes, int n_in,
                              void* d_out, int out_size) {
    const float* x    = (const float*)d_in[0];
    const float* nb   = (const float*)d_in[1];
    const int*   mask = (const int*)  d_in[2];
    const float* We   = (const float*)d_in[3];
    const float* be   = (const float*)d_in[4];
    const float* Wih  = (const float*)d_in[5];
    const float* Whh  = (const float*)d_in[6];
    const float* bih  = (const float*)d_in[7];
    const float* bhh  = (const float*)d_in[8];
    const float* W1   = (const float*)d_in[9];
    const float* b1   = (const float*)d_in[10];
    const float* W2   = (const float*)d_in[11];
    const float* b2   = (const float*)d_in[12];
    const float* Wp   = (const float*)d_in[13];
    const float* bp   = (const float*)d_in[14];
    float* out = (float*)d_out;

    cudaFuncSetAttribute(lstm_fused_kernel, cudaFuncAttributeMaxDynamicSharedMemorySize, SMEM_BYTES);
    cudaFuncSetAttribute(head_kernel, cudaFuncAttributeMaxDynamicSharedMemorySize, H_SMEM_BYTES);

    prep_kernel<<<(12 * 512 * 8 + 255) / 256, 256>>>(Wih, Whh, bih, bhh);
    reset_kernel<<<1, 32>>>();
    append_kernel<<<(NSEQ + 255) / 256, 256>>>(mask);
    pad_kernel<<<(NSEQ + 255) / 256, 256>>>();

    lstm_fused_kernel<<<NSEQ / MTILE, 512, SMEM_BYTES>>>(x, nb, We, be);

    head_kernel<<<BATCH / 8, 256, H_SMEM_BYTES>>>(mask, W1, b1, W2, b2, Wp, bp, out);
}